// round 15
// baseline (speedup 1.0000x reference)
#include <cuda_runtime.h>
#include <cuda_bf16.h>
#include <cuda_fp16.h>
#include <math.h>

#define N_NODES 50000
#define E_EDGES 1600000
#define HID 256
#define F_IN 128
#define NB 64
#define NC 10

// ---------------- static device scratch ----------------
__device__ __nv_bfloat16 d_aggb[(size_t)N_NODES * HID];
__device__ __nv_bfloat16 d_hb1[(size_t)N_NODES * HID];
__device__ __nv_bfloat16 d_hb2[(size_t)N_NODES * HID];
__device__ __nv_bfloat16 d_xb[(size_t)N_NODES * F_IN];
__device__ __align__(16) __half d_xh[(size_t)N_NODES * F_IN];   // fp16 x (gather)
__device__ __align__(16) __half d_hh[(size_t)N_NODES * HID];    // fp16 h (gather)
__device__ __nv_bfloat16 d_wb[327680];
__device__ int   d_deg[N_NODES];
__device__ float d_invdeg[N_NODES];
__device__ int   d_rowptr[N_NODES];
__device__ int   d_cursor[N_NODES];
__device__ int   d_srcs[E_EDGES];
__device__ int   d_counter;
__device__ float d_gate[N_NODES];
__device__ float d_pooled[NB * HID];
__device__ float d_pmax[NB];
__device__ float d_psum[NB];

#define OFF_W1L 0
#define OFF_W1R 32768
#define OFF_W2L 65536
#define OFF_W2R 131072
#define OFF_W3L 196608
#define OFF_W3R 262144
#define W_TOTAL 327680

__device__ __forceinline__ unsigned f2bf2(float a, float b) {
    __nv_bfloat162 p = __floats2bfloat162_rn(a, b);
    return *reinterpret_cast<unsigned*>(&p);
}
__device__ __forceinline__ float2 bf2f(unsigned u) {
    __nv_bfloat162 b = *reinterpret_cast<__nv_bfloat162*>(&u);
    return __bfloat1622float2(b);
}
__device__ __forceinline__ unsigned f2h2u(float a, float b) {
    __half2 h = __floats2half2_rn(a, b);
    return *reinterpret_cast<unsigned*>(&h);
}
__device__ __forceinline__ __half2 u2h2(unsigned u) {
    return *reinterpret_cast<__half2*>(&u);
}
// accumulate 8 fp16 features (one uint4) into 4 half2 accumulators: pure HADD2
__device__ __forceinline__ void acc8h(__half2* acc, uint4 v) {
    acc[0] = __hadd2(acc[0], u2h2(v.x));
    acc[1] = __hadd2(acc[1], u2h2(v.y));
    acc[2] = __hadd2(acc[2], u2h2(v.z));
    acc[3] = __hadd2(acc[3], u2h2(v.w));
}
__device__ __forceinline__ __half2 h2shfl_xor(__half2 v, int m) {
    unsigned u = *reinterpret_cast<unsigned*>(&v);
    u = __shfl_xor_sync(0xffffffff, u, m);
    return *reinterpret_cast<__half2*>(&u);
}
__device__ __forceinline__ int bsearch_batch(const int* batch, int key) {
    int lo = 0, hi = N_NODES;
    while (lo < hi) {
        int mid = (lo + hi) >> 1;
        if (batch[mid] < key) lo = mid + 1; else hi = mid;
    }
    return lo;
}

// ---------------- CSR build (4 edges/thread) ----------------
__global__ void hist_kernel(const int* __restrict__ ei) {
    int e4 = (blockIdx.x * blockDim.x + threadIdx.x) * 4;
    if (e4 >= E_EDGES) return;
    int4 d = *reinterpret_cast<const int4*>(ei + E_EDGES + e4);
    if ((unsigned)d.x < (unsigned)N_NODES) atomicAdd(&d_deg[d.x], 1);
    if ((unsigned)d.y < (unsigned)N_NODES) atomicAdd(&d_deg[d.y], 1);
    if ((unsigned)d.z < (unsigned)N_NODES) atomicAdd(&d_deg[d.z], 1);
    if ((unsigned)d.w < (unsigned)N_NODES) atomicAdd(&d_deg[d.w], 1);
}

__global__ void scan_atomic_kernel() {
    __shared__ int sd[256];
    __shared__ int base;
    int tid = threadIdx.x;
    int i = blockIdx.x * 256 + tid;
    int v = (i < N_NODES) ? d_deg[i] : 0;
    sd[tid] = v;
    __syncthreads();
    for (int off = 1; off < 256; off <<= 1) {
        int t = (tid >= off) ? sd[tid - off] : 0;
        __syncthreads();
        sd[tid] += t;
        __syncthreads();
    }
    if (tid == 255) base = atomicAdd(&d_counter, sd[255]);
    __syncthreads();
    if (i < N_NODES) {
        int excl = base + sd[tid] - v;
        d_rowptr[i] = excl;
        d_cursor[i] = excl;
        d_invdeg[i] = 1.0f / (float)max(v, 1);
    }
}

__global__ void fill_kernel(const int* __restrict__ ei) {
    int e4 = (blockIdx.x * blockDim.x + threadIdx.x) * 4;
    if (e4 >= E_EDGES) return;
    int4 s = *reinterpret_cast<const int4*>(ei + e4);
    int4 d = *reinterpret_cast<const int4*>(ei + E_EDGES + e4);
    if ((unsigned)d.x < (unsigned)N_NODES && (unsigned)s.x < (unsigned)N_NODES)
        d_srcs[atomicAdd(&d_cursor[d.x], 1)] = s.x;
    if ((unsigned)d.y < (unsigned)N_NODES && (unsigned)s.y < (unsigned)N_NODES)
        d_srcs[atomicAdd(&d_cursor[d.y], 1)] = s.y;
    if ((unsigned)d.z < (unsigned)N_NODES && (unsigned)s.z < (unsigned)N_NODES)
        d_srcs[atomicAdd(&d_cursor[d.z], 1)] = s.z;
    if ((unsigned)d.w < (unsigned)N_NODES && (unsigned)s.w < (unsigned)N_NODES)
        d_srcs[atomicAdd(&d_cursor[d.w], 1)] = s.w;
}

// ---------------- converts (+ deg/gate/counter init) ----------------
__global__ void convert_x_kernel(const float* __restrict__ x, const float* __restrict__ bg) {
    int i = blockIdx.x * blockDim.x + threadIdx.x;
    if (i == 0) d_counter = 0;
    if (i < N_NODES) { d_deg[i] = 0; d_gate[i] = bg[0]; }
    if (i >= N_NODES * F_IN / 4) return;
    float4 v = reinterpret_cast<const float4*>(x)[i];
    uint2 o;
    o.x = f2bf2(v.x, v.y);
    o.y = f2bf2(v.z, v.w);
    reinterpret_cast<uint2*>(d_xb)[i] = o;
    uint2 oh;
    oh.x = f2h2u(v.x, v.y);
    oh.y = f2h2u(v.z, v.w);
    reinterpret_cast<uint2*>(d_xh)[i] = oh;
}

__global__ void convert_w_kernel(const float* __restrict__ W1l, const float* __restrict__ W1r,
                                 const float* __restrict__ W2l, const float* __restrict__ W2r,
                                 const float* __restrict__ W3l, const float* __restrict__ W3r) {
    int i = blockIdx.x * blockDim.x + threadIdx.x;
    if (i >= W_TOTAL) return;
    float v;
    if      (i < OFF_W1R) v = W1l[i - OFF_W1L];
    else if (i < OFF_W2L) v = W1r[i - OFF_W1R];
    else if (i < OFF_W2R) v = W2l[i - OFF_W2L];
    else if (i < OFF_W3L) v = W2r[i - OFF_W2R];
    else if (i < OFF_W3R) v = W3l[i - OFF_W3L];
    else                  v = W3r[i - OFF_W3R];
    d_wb[i] = __float2bfloat16_rn(v);
}

// ---------------- warp-per-node fp16 gather, K=256 ----------------
// 32 lanes x uint4(8 half) = full 512B row per neighbor; fully warp-uniform flow
__global__ __launch_bounds__(256) void aggregate_h16_k256(const __half* __restrict__ xin,
                                                          __nv_bfloat16* __restrict__ agg) {
    int wid = threadIdx.x >> 5;
    int n = blockIdx.x * 8 + wid;
    if (n >= N_NODES) return;
    int lane = threadIdx.x & 31;
    int beg = d_rowptr[n], end = beg + d_deg[n];
    const uint4* __restrict__ x4 = reinterpret_cast<const uint4*>(xin);

    __half2 acc[4];
#pragma unroll
    for (int k = 0; k < 4; k++) acc[k] = __half2half2(__ushort_as_half(0));

    for (int base = beg; base < end; base += 32) {
        int cnt = min(32, end - base);
        int my = (lane < cnt) ? d_srcs[base + lane] : 0;
        int j = 0;
        for (; j + 4 <= cnt; j += 4) {
            int s0 = __shfl_sync(0xffffffff, my, j);
            int s1 = __shfl_sync(0xffffffff, my, j + 1);
            int s2 = __shfl_sync(0xffffffff, my, j + 2);
            int s3 = __shfl_sync(0xffffffff, my, j + 3);
            uint4 v0 = x4[(size_t)s0 * 32 + lane];
            uint4 v1 = x4[(size_t)s1 * 32 + lane];
            uint4 v2 = x4[(size_t)s2 * 32 + lane];
            uint4 v3 = x4[(size_t)s3 * 32 + lane];
            acc8h(acc, v0); acc8h(acc, v1); acc8h(acc, v2); acc8h(acc, v3);
        }
        for (; j < cnt; j++) {
            int s = __shfl_sync(0xffffffff, my, j);
            acc8h(acc, x4[(size_t)s * 32 + lane]);
        }
    }

    float inv = d_invdeg[n];
    float f[8];
#pragma unroll
    for (int k = 0; k < 4; k++) {
        float2 t = __half22float2(acc[k]);
        f[2 * k] = t.x * inv;
        f[2 * k + 1] = t.y * inv;
    }
    uint4 o;
    o.x = f2bf2(f[0], f[1]);
    o.y = f2bf2(f[2], f[3]);
    o.z = f2bf2(f[4], f[5]);
    o.w = f2bf2(f[6], f[7]);
    reinterpret_cast<uint4*>(agg)[(size_t)n * 32 + lane] = o;
}

// ---------------- warp-per-node fp16 gather, K=128 ----------------
// 16 slots x 2 groups; uniform shfl flow, guarded loads
__global__ __launch_bounds__(256) void aggregate_h16_k128(const __half* __restrict__ xin,
                                                          __nv_bfloat16* __restrict__ agg) {
    int wid = threadIdx.x >> 5;
    int n = blockIdx.x * 8 + wid;
    if (n >= N_NODES) return;
    int lane = threadIdx.x & 31;
    int slot = lane & 15, grp = lane >> 4;
    int beg = d_rowptr[n], end = beg + d_deg[n];
    const uint4* __restrict__ x4 = reinterpret_cast<const uint4*>(xin);

    __half2 acc[4];
#pragma unroll
    for (int k = 0; k < 4; k++) acc[k] = __half2half2(__ushort_as_half(0));

    for (int base = beg; base < end; base += 32) {
        int cnt = min(32, end - base);
        int my = (lane < cnt) ? d_srcs[base + lane] : 0;
        for (int jb = 0; jb < cnt; jb += 8) {
            int j0 = jb + grp, j1 = jb + 2 + grp, j2 = jb + 4 + grp, j3 = jb + 6 + grp;
            int s0 = __shfl_sync(0xffffffff, my, j0);
            int s1 = __shfl_sync(0xffffffff, my, j1);
            int s2 = __shfl_sync(0xffffffff, my, j2);
            int s3 = __shfl_sync(0xffffffff, my, j3);
            if (j3 < cnt) {
                acc8h(acc, x4[(size_t)s0 * 16 + slot]);
                acc8h(acc, x4[(size_t)s1 * 16 + slot]);
                acc8h(acc, x4[(size_t)s2 * 16 + slot]);
                acc8h(acc, x4[(size_t)s3 * 16 + slot]);
            } else {
                if (j0 < cnt) acc8h(acc, x4[(size_t)s0 * 16 + slot]);
                if (j1 < cnt) acc8h(acc, x4[(size_t)s1 * 16 + slot]);
                if (j2 < cnt) acc8h(acc, x4[(size_t)s2 * 16 + slot]);
            }
        }
    }

#pragma unroll
    for (int k = 0; k < 4; k++) acc[k] = __hadd2(acc[k], h2shfl_xor(acc[k], 16));

    if (grp == 0) {
        float inv = d_invdeg[n];
        float f[8];
#pragma unroll
        for (int k = 0; k < 4; k++) {
            float2 t = __half22float2(acc[k]);
            f[2 * k] = t.x * inv;
            f[2 * k + 1] = t.y * inv;
        }
        uint4 o;
        o.x = f2bf2(f[0], f[1]);
        o.y = f2bf2(f[2], f[3]);
        o.z = f2bf2(f[4], f[5]);
        o.w = f2bf2(f[6], f[7]);
        reinterpret_cast<uint4*>(agg)[(size_t)n * 16 + slot] = o;
    }
}

// ---------------- bf16 tensor-core fused SAGE linear ----------------
__device__ __forceinline__ void mma_bf16(float c[4], const unsigned a[4], const unsigned b[2]) {
    asm volatile(
        "mma.sync.aligned.m16n8k16.row.col.f32.bf16.bf16.f32 "
        "{%0,%1,%2,%3}, {%4,%5,%6,%7}, {%8,%9}, {%0,%1,%2,%3};"
        : "+f"(c[0]), "+f"(c[1]), "+f"(c[2]), "+f"(c[3])
        : "r"(a[0]), "r"(a[1]), "r"(a[2]), "r"(a[3]), "r"(b[0]), "r"(b[1]));
}

__global__ __launch_bounds__(256) void sage_linear_bf16(
    const __nv_bfloat16* __restrict__ A0, const __nv_bfloat16* __restrict__ A1,
    const __nv_bfloat16* __restrict__ W0, const __nv_bfloat16* __restrict__ W1,
    const float* __restrict__ bias,
    __nv_bfloat16* __restrict__ outb, __half* __restrict__ outh,
    const float* __restrict__ Wgate, float* __restrict__ gate,
    int M, int Ka)
{
    __shared__ unsigned As2[128][36];
    __shared__ unsigned Ws2[64][36];
    int tid = threadIdx.x;
    int wid = tid >> 5, lane = tid & 31;
    int wm = wid & 3, wn = wid >> 2;
    int g = lane >> 2, tg = lane & 3;
    int bm = blockIdx.x, bn = blockIdx.y;

    const int nk = Ka >> 6;
    const int nt = 2 * nk;

    int arow[4], ac8[4], wrow[2], wc8[2];
#pragma unroll
    for (int i = 0; i < 4; i++) {
        int l = tid + i * 256;
        arow[i] = l >> 3; ac8[i] = l & 7;
    }
#pragma unroll
    for (int i = 0; i < 2; i++) {
        int l = tid + i * 256;
        wrow[i] = l >> 3; wc8[i] = l & 7;
    }

    uint4 ra[4], rw[2];
    auto load_tile = [&](int it) {
        const __nv_bfloat16* Asrc = (it < nk) ? A0 : A1;
        const __nv_bfloat16* Wsrc = (it < nk) ? W0 : W1;
        int kb = (it >= nk ? it - nk : it) << 6;
#pragma unroll
        for (int i = 0; i < 4; i++) {
            int gr = bm * 128 + arow[i];
            ra[i] = make_uint4(0u, 0u, 0u, 0u);
            if (gr < M) ra[i] = *reinterpret_cast<const uint4*>(Asrc + (size_t)gr * Ka + kb + ac8[i] * 8);
        }
#pragma unroll
        for (int i = 0; i < 2; i++) {
            int gj = bn * 64 + wrow[i];
            rw[i] = *reinterpret_cast<const uint4*>(Wsrc + (size_t)gj * Ka + kb + wc8[i] * 8);
        }
    };
    auto store_tile = [&]() {
#pragma unroll
        for (int i = 0; i < 4; i++)
            *reinterpret_cast<uint4*>(&As2[arow[i]][ac8[i] * 4]) = ra[i];
#pragma unroll
        for (int i = 0; i < 2; i++)
            *reinterpret_cast<uint4*>(&Ws2[wrow[i]][wc8[i] * 4]) = rw[i];
    };

    float c[2][4][4];
#pragma unroll
    for (int i = 0; i < 2; i++)
#pragma unroll
        for (int j = 0; j < 4; j++)
#pragma unroll
            for (int k = 0; k < 4; k++) c[i][j][k] = 0.f;

    load_tile(0);
    store_tile();
    __syncthreads();

    for (int it = 0; it < nt; it++) {
        if (it + 1 < nt) load_tile(it + 1);
#pragma unroll
        for (int kk2 = 0; kk2 < 32; kk2 += 8) {
            unsigned a[2][4], bfr[4][2];
#pragma unroll
            for (int mi = 0; mi < 2; mi++) {
                int rm = wm * 32 + mi * 16;
                a[mi][0] = As2[rm + g][kk2 + tg];
                a[mi][1] = As2[rm + g + 8][kk2 + tg];
                a[mi][2] = As2[rm + g][kk2 + tg + 4];
                a[mi][3] = As2[rm + g + 8][kk2 + tg + 4];
            }
#pragma unroll
            for (int ni = 0; ni < 4; ni++) {
                int jn = wn * 32 + ni * 8 + g;
                bfr[ni][0] = Ws2[jn][kk2 + tg];
                bfr[ni][1] = Ws2[jn][kk2 + tg + 4];
            }
#pragma unroll
            for (int mi = 0; mi < 2; mi++)
#pragma unroll
                for (int ni = 0; ni < 4; ni++)
                    mma_bf16(c[mi][ni], a[mi], bfr[ni]);
        }
        __syncthreads();
        if (it + 1 < nt) {
            store_tile();
            __syncthreads();
        }
    }

#pragma unroll
    for (int mi = 0; mi < 2; mi++) {
        int row0 = bm * 128 + wm * 32 + mi * 16 + g;
        int row1 = row0 + 8;
        float gp0 = 0.f, gp1 = 0.f;
#pragma unroll
        for (int ni = 0; ni < 4; ni++) {
            int col = bn * 64 + wn * 32 + ni * 8 + 2 * tg;
            float b0 = bias[col], b1v = bias[col + 1];
            float v00 = fmaxf(c[mi][ni][0] + b0, 0.f);
            float v01 = fmaxf(c[mi][ni][1] + b1v, 0.f);
            float v10 = fmaxf(c[mi][ni][2] + b0, 0.f);
            float v11 = fmaxf(c[mi][ni][3] + b1v, 0.f);
            if (Wgate) {
                float w0 = Wgate[col], w1 = Wgate[col + 1];
                gp0 += v00 * w0 + v01 * w1;
                gp1 += v10 * w0 + v11 * w1;
            }
            if (row0 < M) {
                if (outb)
                    reinterpret_cast<unsigned*>(outb)[((size_t)row0 * HID + col) >> 1] = f2bf2(v00, v01);
                if (outh)
                    reinterpret_cast<unsigned*>(outh)[((size_t)row0 * HID + col) >> 1] = f2h2u(v00, v01);
            }
            if (row1 < M) {
                if (outb)
                    reinterpret_cast<unsigned*>(outb)[((size_t)row1 * HID + col) >> 1] = f2bf2(v10, v11);
                if (outh)
                    reinterpret_cast<unsigned*>(outh)[((size_t)row1 * HID + col) >> 1] = f2h2u(v10, v11);
            }
        }
        if (Wgate) {
            gp0 += __shfl_xor_sync(0xffffffff, gp0, 1);
            gp0 += __shfl_xor_sync(0xffffffff, gp0, 2);
            gp1 += __shfl_xor_sync(0xffffffff, gp1, 1);
            gp1 += __shfl_xor_sync(0xffffffff, gp1, 2);
            if (tg == 0) {
                if (row0 < M) atomicAdd(&gate[row0], gp0);
                if (row1 < M) atomicAdd(&gate[row1], gp1);
            }
        }
    }
}

// ---------------- pool stats ----------------
__global__ void pool_stats_kernel(const float* __restrict__ gate, const int* __restrict__ batch) {
    int b = blockIdx.x, tid = threadIdx.x;
    __shared__ int sb[2];
    if (tid < 2) sb[tid] = bsearch_batch(batch, b + tid);
    __syncthreads();
    int beg = sb[0], end = sb[1];
    __shared__ float red[256];

    float m = -3.4e38f;
    for (int n = beg + tid; n < end; n += 256) m = fmaxf(m, gate[n]);
    red[tid] = m; __syncthreads();
    for (int o = 128; o > 0; o >>= 1) { if (tid < o) red[tid] = fmaxf(red[tid], red[tid + o]); __syncthreads(); }
    float mx = red[0]; __syncthreads();

    float s = 0.f;
    for (int n = beg + tid; n < end; n += 256) s += expf(gate[n] - mx);
    red[tid] = s; __syncthreads();
    for (int o = 128; o > 0; o >>= 1) { if (tid < o) red[tid] += red[tid + o]; __syncthreads(); }

    if (tid == 0) { d_pmax[b] = mx; d_psum[b] = fmaxf(red[0], 1e-38f); }
    d_pooled[b * HID + tid] = 0.f;
}

// ---------------- pool accumulate (bf16 h) ----------------
#define PSPLIT 8
__global__ __launch_bounds__(64) void pool_acc_kernel(const __nv_bfloat16* __restrict__ h,
                                                      const float* __restrict__ gate,
                                                      const int* __restrict__ batch) {
    int b = blockIdx.x, sp = blockIdx.y, t = threadIdx.x;
    __shared__ int sb[2];
    if (t < 2) sb[t] = bsearch_batch(batch, b + t);
    __syncthreads();
    int beg = sb[0], end = sb[1];
    float mx = d_pmax[b];
    float inv = 1.0f / d_psum[b];
    const uint2* h2 = reinterpret_cast<const uint2*>(h);
    float a0 = 0.f, a1 = 0.f, a2 = 0.f, a3 = 0.f;
    for (int n = beg + sp; n < end; n += PSPLIT) {
        float w = __expf(gate[n] - mx) * inv;
        uint2 v = h2[(size_t)n * 64 + t];
        float2 f0 = bf2f(v.x), f1 = bf2f(v.y);
        a0 += w * f0.x; a1 += w * f0.y; a2 += w * f1.x; a3 += w * f1.y;
    }
    float* p = &d_pooled[b * HID + t * 4];
    atomicAdd(p + 0, a0);
    atomicAdd(p + 1, a1);
    atomicAdd(p + 2, a2);
    atomicAdd(p + 3, a3);
}

// ---------------- MLP head + log_softmax ----------------
__global__ void head_kernel(const float* __restrict__ W1, const float* __restrict__ b1,
                            const float* __restrict__ W2, const float* __restrict__ b2,
                            float* __restrict__ out) {
    int b = blockIdx.x, t = threadIdx.x;
    __shared__ float pin[HID], m1[HID];
    __shared__ float logits[NC];
    pin[t] = d_pooled[b * HID + t];
    __syncthreads();
    float acc = b1[t];
#pragma unroll 8
    for (int k = 0; k < HID; k++) acc += pin[k] * W1[t * HID + k];
    m1[t] = fmaxf(acc, 0.f);
    __syncthreads();
    if (t < NC) {
        float a = b2[t];
        for (int k = 0; k < HID; k++) a += m1[k] * W2[t * HID + k];
        logits[t] = a;
    }
    __syncthreads();
    if (t == 0) {
        float mx = logits[0];
        for (int c2 = 1; c2 < NC; c2++) mx = fmaxf(mx, logits[c2]);
        float s = 0.f;
        for (int c2 = 0; c2 < NC; c2++) s += expf(logits[c2] - mx);
        float lse = mx + logf(s);
        for (int c2 = 0; c2 < NC; c2++) out[b * NC + c2] = logits[c2] - lse;
    }
}

// ---------------- launch ----------------
extern "C" void kernel_launch(void* const* d_in, const int* in_sizes, int n_in,
                              void* d_out, int out_size) {
    const float* x      = (const float*)d_in[0];
    const int* ei       = (const int*)d_in[1];
    const int* batch    = (const int*)d_in[2];
    const float* W1l = (const float*)d_in[3];
    const float* b1l = (const float*)d_in[4];
    const float* W1r = (const float*)d_in[5];
    const float* W2l = (const float*)d_in[6];
    const float* b2l = (const float*)d_in[7];
    const float* W2r = (const float*)d_in[8];
    const float* W3l = (const float*)d_in[9];
    const float* b3l = (const float*)d_in[10];
    const float* W3r = (const float*)d_in[11];
    const float* Wg  = (const float*)d_in[12];
    const float* bg  = (const float*)d_in[13];
    const float* Wl1 = (const float*)d_in[14];
    const float* bl1 = (const float*)d_in[15];
    const float* Wl2 = (const float*)d_in[16];
    const float* bl2 = (const float*)d_in[17];
    float* out = (float*)d_out;

    void *p_aggb_, *p_hb1_, *p_hb2_, *p_xb_, *p_xh_, *p_hh_, *p_wb_, *p_gate_;
    cudaGetSymbolAddress(&p_aggb_, d_aggb);
    cudaGetSymbolAddress(&p_hb1_, d_hb1);
    cudaGetSymbolAddress(&p_hb2_, d_hb2);
    cudaGetSymbolAddress(&p_xb_, d_xb);
    cudaGetSymbolAddress(&p_xh_, d_xh);
    cudaGetSymbolAddress(&p_hh_, d_hh);
    cudaGetSymbolAddress(&p_wb_, d_wb);
    cudaGetSymbolAddress(&p_gate_, d_gate);
    __nv_bfloat16* p_aggb = (__nv_bfloat16*)p_aggb_;
    __nv_bfloat16* p_hb1 = (__nv_bfloat16*)p_hb1_;
    __nv_bfloat16* p_hb2 = (__nv_bfloat16*)p_hb2_;
    __nv_bfloat16* p_xb = (__nv_bfloat16*)p_xb_;
    __half* p_xh = (__half*)p_xh_;
    __half* p_hh = (__half*)p_hh_;
    __nv_bfloat16* p_wb = (__nv_bfloat16*)p_wb_;
    float* p_gate = (float*)p_gate_;

    const int e4blocks = (E_EDGES / 4 + 255) / 256;
    const int nwarp_blocks = (N_NODES + 7) / 8;
    const int nscan_blocks = (N_NODES + 255) / 256;

    // converts + init
    convert_x_kernel<<<(N_NODES * F_IN / 4 + 255) / 256, 256>>>(x, bg);
    convert_w_kernel<<<(W_TOTAL + 255) / 256, 256>>>(W1l, W1r, W2l, W2r, W3l, W3r);

    // CSR build
    hist_kernel<<<e4blocks, 256>>>(ei);
    scan_atomic_kernel<<<nscan_blocks, 256>>>();
    fill_kernel<<<e4blocks, 256>>>(ei);

    dim3 gemm_grid((N_NODES + 127) / 128, HID / 64);

    // layer 1
    aggregate_h16_k128<<<nwarp_blocks, 256>>>(p_xh, p_aggb);
    sage_linear_bf16<<<gemm_grid, 256>>>(p_aggb, p_xb, p_wb + OFF_W1L, p_wb + OFF_W1R,
                                         b1l, p_hb1, p_hh, nullptr, nullptr, N_NODES, F_IN);
    // layer 2
    aggregate_h16_k256<<<nwarp_blocks, 256>>>(p_hh, p_aggb);
    sage_linear_bf16<<<gemm_grid, 256>>>(p_aggb, p_hb1, p_wb + OFF_W2L, p_wb + OFF_W2R,
                                         b2l, p_hb2, p_hh, nullptr, nullptr, N_NODES, HID);
    // layer 3: bf16 h3 into hb1 + fused gate
    aggregate_h16_k256<<<nwarp_blocks, 256>>>(p_hh, p_aggb);
    sage_linear_bf16<<<gemm_grid, 256>>>(p_aggb, p_hb2, p_wb + OFF_W3L, p_wb + OFF_W3R,
                                         b3l, p_hb1, nullptr, Wg, p_gate, N_NODES, HID);

    // pooling + head
    pool_stats_kernel<<<NB, 256>>>(p_gate, batch);
    pool_acc_kernel<<<dim3(NB, PSPLIT), 64>>>(p_hb1, p_gate, batch);
    head_kernel<<<NB, HID>>>(Wl1, bl1, Wl2, bl2, out);
}

// round 16
// speedup vs baseline: 1.0481x; 1.0481x over previous
#include <cuda_runtime.h>
#include <cuda_bf16.h>
#include <cuda_fp16.h>
#include <cuda_fp8.h>
#include <math.h>

#define N_NODES 50000
#define E_EDGES 1600000
#define HID 256
#define F_IN 128
#define NB 64
#define NC 10

// ---------------- static device scratch ----------------
__device__ __nv_bfloat16 d_aggb[(size_t)N_NODES * HID];
__device__ __nv_bfloat16 d_hb1[(size_t)N_NODES * HID];
__device__ __nv_bfloat16 d_hb2[(size_t)N_NODES * HID];
__device__ __nv_bfloat16 d_xb[(size_t)N_NODES * F_IN];
__device__ __align__(16) unsigned char d_xf8[(size_t)N_NODES * F_IN];
__device__ __align__(16) unsigned char d_hf8[(size_t)N_NODES * HID];
__device__ __nv_bfloat16 d_wb[327680];
__device__ int   d_deg[N_NODES];
__device__ float d_invdeg[N_NODES];
__device__ int   d_rowptr[N_NODES];
__device__ int   d_cursor[N_NODES];
__device__ int   d_srcs[E_EDGES];
__device__ int   d_counter;
__device__ float d_gate[N_NODES];
__device__ float d_pooled[NB * HID];
__device__ float d_pmax[NB];
__device__ float d_psum[NB];

#define OFF_W1L 0
#define OFF_W1R 32768
#define OFF_W2L 65536
#define OFF_W2R 131072
#define OFF_W3L 196608
#define OFF_W3R 262144
#define W_TOTAL 327680

__device__ __forceinline__ unsigned f2bf2(float a, float b) {
    __nv_bfloat162 p = __floats2bfloat162_rn(a, b);
    return *reinterpret_cast<unsigned*>(&p);
}
__device__ __forceinline__ float2 bf2f(unsigned u) {
    __nv_bfloat162 b = *reinterpret_cast<__nv_bfloat162*>(&u);
    return __bfloat1622float2(b);
}
__device__ __forceinline__ __half2 fp8x2_to_h2(unsigned short u) {
    __half2_raw hr = __nv_cvt_fp8x2_to_halfraw2((__nv_fp8x2_storage_t)u, __NV_E4M3);
    return *reinterpret_cast<__half2*>(&hr);
}
__device__ __forceinline__ unsigned short f2_to_fp8x2(float a, float b) {
    float2 f = make_float2(a, b);
    return (unsigned short)__nv_cvt_float2_to_fp8x2(f, __NV_SATFINITE, __NV_E4M3);
}
// accumulate 16 fp8 features into 8 half2 accumulators: 1 op/feature
__device__ __forceinline__ void acc16h(__half2* acc, uint4 v) {
    unsigned w[4] = {v.x, v.y, v.z, v.w};
#pragma unroll
    for (int q = 0; q < 4; q++) {
        acc[2 * q]     = __hadd2(acc[2 * q],     fp8x2_to_h2((unsigned short)w[q]));
        acc[2 * q + 1] = __hadd2(acc[2 * q + 1], fp8x2_to_h2((unsigned short)(w[q] >> 16)));
    }
}
__device__ __forceinline__ __half2 h2shfl_xor(__half2 v, int m) {
    unsigned u = *reinterpret_cast<unsigned*>(&v);
    u = __shfl_xor_sync(0xffffffff, u, m);
    return *reinterpret_cast<__half2*>(&u);
}
__device__ __forceinline__ int bsearch_batch(const int* batch, int key) {
    int lo = 0, hi = N_NODES;
    while (lo < hi) {
        int mid = (lo + hi) >> 1;
        if (batch[mid] < key) lo = mid + 1; else hi = mid;
    }
    return lo;
}

// ---------------- CSR build (4 edges/thread) ----------------
__global__ void hist_kernel(const int* __restrict__ ei) {
    int e4 = (blockIdx.x * blockDim.x + threadIdx.x) * 4;
    if (e4 >= E_EDGES) return;
    int4 d = *reinterpret_cast<const int4*>(ei + E_EDGES + e4);
    if ((unsigned)d.x < (unsigned)N_NODES) atomicAdd(&d_deg[d.x], 1);
    if ((unsigned)d.y < (unsigned)N_NODES) atomicAdd(&d_deg[d.y], 1);
    if ((unsigned)d.z < (unsigned)N_NODES) atomicAdd(&d_deg[d.z], 1);
    if ((unsigned)d.w < (unsigned)N_NODES) atomicAdd(&d_deg[d.w], 1);
}

__global__ void scan_atomic_kernel() {
    __shared__ int sd[256];
    __shared__ int base;
    int tid = threadIdx.x;
    int i = blockIdx.x * 256 + tid;
    int v = (i < N_NODES) ? d_deg[i] : 0;
    sd[tid] = v;
    __syncthreads();
    for (int off = 1; off < 256; off <<= 1) {
        int t = (tid >= off) ? sd[tid - off] : 0;
        __syncthreads();
        sd[tid] += t;
        __syncthreads();
    }
    if (tid == 255) base = atomicAdd(&d_counter, sd[255]);
    __syncthreads();
    if (i < N_NODES) {
        int excl = base + sd[tid] - v;
        d_rowptr[i] = excl;
        d_cursor[i] = excl;
        d_invdeg[i] = 1.0f / (float)max(v, 1);
    }
}

__global__ void fill_kernel(const int* __restrict__ ei) {
    int e4 = (blockIdx.x * blockDim.x + threadIdx.x) * 4;
    if (e4 >= E_EDGES) return;
    int4 s = *reinterpret_cast<const int4*>(ei + e4);
    int4 d = *reinterpret_cast<const int4*>(ei + E_EDGES + e4);
    if ((unsigned)d.x < (unsigned)N_NODES && (unsigned)s.x < (unsigned)N_NODES)
        d_srcs[atomicAdd(&d_cursor[d.x], 1)] = s.x;
    if ((unsigned)d.y < (unsigned)N_NODES && (unsigned)s.y < (unsigned)N_NODES)
        d_srcs[atomicAdd(&d_cursor[d.y], 1)] = s.y;
    if ((unsigned)d.z < (unsigned)N_NODES && (unsigned)s.z < (unsigned)N_NODES)
        d_srcs[atomicAdd(&d_cursor[d.z], 1)] = s.z;
    if ((unsigned)d.w < (unsigned)N_NODES && (unsigned)s.w < (unsigned)N_NODES)
        d_srcs[atomicAdd(&d_cursor[d.w], 1)] = s.w;
}

// ---------------- converts (+ deg/gate/counter init) ----------------
__global__ void convert_x_kernel(const float* __restrict__ x, const float* __restrict__ bg) {
    int i = blockIdx.x * blockDim.x + threadIdx.x;
    if (i == 0) d_counter = 0;
    if (i < N_NODES) { d_deg[i] = 0; d_gate[i] = bg[0]; }
    if (i >= N_NODES * F_IN / 4) return;
    float4 v = reinterpret_cast<const float4*>(x)[i];
    uint2 o;
    o.x = f2bf2(v.x, v.y);
    o.y = f2bf2(v.z, v.w);
    reinterpret_cast<uint2*>(d_xb)[i] = o;
    unsigned p8 = (unsigned)f2_to_fp8x2(v.x, v.y) | ((unsigned)f2_to_fp8x2(v.z, v.w) << 16);
    reinterpret_cast<unsigned*>(d_xf8)[i] = p8;
}

__global__ void convert_w_kernel(const float* __restrict__ W1l, const float* __restrict__ W1r,
                                 const float* __restrict__ W2l, const float* __restrict__ W2r,
                                 const float* __restrict__ W3l, const float* __restrict__ W3r) {
    int i = blockIdx.x * blockDim.x + threadIdx.x;
    if (i >= W_TOTAL) return;
    float v;
    if      (i < OFF_W1R) v = W1l[i - OFF_W1L];
    else if (i < OFF_W2L) v = W1r[i - OFF_W1R];
    else if (i < OFF_W2R) v = W2l[i - OFF_W2L];
    else if (i < OFF_W3L) v = W2r[i - OFF_W2R];
    else if (i < OFF_W3R) v = W3l[i - OFF_W3L];
    else                  v = W3r[i - OFF_W3R];
    d_wb[i] = __float2bfloat16_rn(v);
}

// ---------------- warp-per-node fp8 gather (half2 accumulate), K=256 ----------------
__global__ __launch_bounds__(256) void aggregate_fp8_warp_k256(const unsigned char* __restrict__ xin,
                                                               __nv_bfloat16* __restrict__ agg) {
    int wid = threadIdx.x >> 5;
    int n = blockIdx.x * 8 + wid;
    if (n >= N_NODES) return;
    int lane = threadIdx.x & 31;
    int slot = lane & 15, grp = lane >> 4;
    int beg = d_rowptr[n], end = beg + d_deg[n];
    const uint4* __restrict__ x4 = reinterpret_cast<const uint4*>(xin);

    __half2 acc[8];
#pragma unroll
    for (int k = 0; k < 8; k++) acc[k] = __half2half2(__ushort_as_half(0));

    for (int base = beg; base < end; base += 32) {
        int cnt = min(32, end - base);
        int my = (lane < cnt) ? d_srcs[base + lane] : 0;
        for (int jb = 0; jb < cnt; jb += 8) {
            int j0 = jb + grp, j1 = jb + 2 + grp, j2 = jb + 4 + grp, j3 = jb + 6 + grp;
            int s0 = __shfl_sync(0xffffffff, my, j0);
            int s1 = __shfl_sync(0xffffffff, my, j1);
            int s2 = __shfl_sync(0xffffffff, my, j2);
            int s3 = __shfl_sync(0xffffffff, my, j3);
            if (j3 < cnt) {
                acc16h(acc, x4[(size_t)s0 * 16 + slot]);
                acc16h(acc, x4[(size_t)s1 * 16 + slot]);
                acc16h(acc, x4[(size_t)s2 * 16 + slot]);
                acc16h(acc, x4[(size_t)s3 * 16 + slot]);
            } else {
                if (j0 < cnt) acc16h(acc, x4[(size_t)s0 * 16 + slot]);
                if (j1 < cnt) acc16h(acc, x4[(size_t)s1 * 16 + slot]);
                if (j2 < cnt) acc16h(acc, x4[(size_t)s2 * 16 + slot]);
            }
        }
    }

#pragma unroll
    for (int k = 0; k < 8; k++) acc[k] = __hadd2(acc[k], h2shfl_xor(acc[k], 16));

    if (grp == 0) {
        float inv = d_invdeg[n];
        float f[16];
#pragma unroll
        for (int k = 0; k < 8; k++) {
            float2 t = __half22float2(acc[k]);
            f[2 * k] = t.x * inv;
            f[2 * k + 1] = t.y * inv;
        }
        uint4 o0, o1;
        o0.x = f2bf2(f[0], f[1]);   o0.y = f2bf2(f[2], f[3]);
        o0.z = f2bf2(f[4], f[5]);   o0.w = f2bf2(f[6], f[7]);
        o1.x = f2bf2(f[8], f[9]);   o1.y = f2bf2(f[10], f[11]);
        o1.z = f2bf2(f[12], f[13]); o1.w = f2bf2(f[14], f[15]);
        uint4* ag4 = reinterpret_cast<uint4*>(agg);
        ag4[(size_t)n * 32 + slot * 2]     = o0;
        ag4[(size_t)n * 32 + slot * 2 + 1] = o1;
    }
}

// ---------------- warp-per-node fp8 gather (half2 accumulate), K=128 ----------------
__global__ __launch_bounds__(256) void aggregate_fp8_warp_k128(const unsigned char* __restrict__ xin,
                                                               __nv_bfloat16* __restrict__ agg) {
    int wid = threadIdx.x >> 5;
    int n = blockIdx.x * 8 + wid;
    if (n >= N_NODES) return;
    int lane = threadIdx.x & 31;
    int slot = lane & 7, grp = lane >> 3;
    int beg = d_rowptr[n], end = beg + d_deg[n];
    const uint4* __restrict__ x4 = reinterpret_cast<const uint4*>(xin);

    __half2 acc[8];
#pragma unroll
    for (int k = 0; k < 8; k++) acc[k] = __half2half2(__ushort_as_half(0));

    for (int base = beg; base < end; base += 32) {
        int cnt = min(32, end - base);
        int my = (lane < cnt) ? d_srcs[base + lane] : 0;
        for (int jb = 0; jb < cnt; jb += 8) {
            int j0 = jb + grp, j1 = jb + 4 + grp;
            int s0 = __shfl_sync(0xffffffff, my, j0);
            int s1 = __shfl_sync(0xffffffff, my, j1);
            if (j1 < cnt) {
                acc16h(acc, x4[(size_t)s0 * 8 + slot]);
                acc16h(acc, x4[(size_t)s1 * 8 + slot]);
            } else if (j0 < cnt) {
                acc16h(acc, x4[(size_t)s0 * 8 + slot]);
            }
        }
    }

#pragma unroll
    for (int k = 0; k < 8; k++) {
        acc[k] = __hadd2(acc[k], h2shfl_xor(acc[k], 8));
        acc[k] = __hadd2(acc[k], h2shfl_xor(acc[k], 16));
    }

    if (grp == 0) {
        float inv = d_invdeg[n];
        float f[16];
#pragma unroll
        for (int k = 0; k < 8; k++) {
            float2 t = __half22float2(acc[k]);
            f[2 * k] = t.x * inv;
            f[2 * k + 1] = t.y * inv;
        }
        uint4 o0, o1;
        o0.x = f2bf2(f[0], f[1]);   o0.y = f2bf2(f[2], f[3]);
        o0.z = f2bf2(f[4], f[5]);   o0.w = f2bf2(f[6], f[7]);
        o1.x = f2bf2(f[8], f[9]);   o1.y = f2bf2(f[10], f[11]);
        o1.z = f2bf2(f[12], f[13]); o1.w = f2bf2(f[14], f[15]);
        uint4* ag4 = reinterpret_cast<uint4*>(agg);
        ag4[(size_t)n * 16 + slot * 2]     = o0;
        ag4[(size_t)n * 16 + slot * 2 + 1] = o1;
    }
}

// ---------------- bf16 tensor-core fused SAGE linear (register-staged double buffer) ----------------
__device__ __forceinline__ void mma_bf16(float c[4], const unsigned a[4], const unsigned b[2]) {
    asm volatile(
        "mma.sync.aligned.m16n8k16.row.col.f32.bf16.bf16.f32 "
        "{%0,%1,%2,%3}, {%4,%5,%6,%7}, {%8,%9}, {%0,%1,%2,%3};"
        : "+f"(c[0]), "+f"(c[1]), "+f"(c[2]), "+f"(c[3])
        : "r"(a[0]), "r"(a[1]), "r"(a[2]), "r"(a[3]), "r"(b[0]), "r"(b[1]));
}

__global__ __launch_bounds__(256) void sage_linear_bf16(
    const __nv_bfloat16* __restrict__ A0, const __nv_bfloat16* __restrict__ A1,
    const __nv_bfloat16* __restrict__ W0, const __nv_bfloat16* __restrict__ W1,
    const float* __restrict__ bias,
    __nv_bfloat16* __restrict__ outb, unsigned char* __restrict__ outf8,
    const float* __restrict__ Wgate, float* __restrict__ gate,
    int M, int Ka)
{
    __shared__ unsigned As2[128][36];
    __shared__ unsigned Ws2[64][36];
    int tid = threadIdx.x;
    int wid = tid >> 5, lane = tid & 31;
    int wm = wid & 3, wn = wid >> 2;
    int g = lane >> 2, tg = lane & 3;
    int bm = blockIdx.x, bn = blockIdx.y;

    const int nk = Ka >> 6;
    const int nt = 2 * nk;

    int arow[4], ac8[4], wrow[2], wc8[2];
#pragma unroll
    for (int i = 0; i < 4; i++) {
        int l = tid + i * 256;
        arow[i] = l >> 3; ac8[i] = l & 7;
    }
#pragma unroll
    for (int i = 0; i < 2; i++) {
        int l = tid + i * 256;
        wrow[i] = l >> 3; wc8[i] = l & 7;
    }

    uint4 ra[4], rw[2];
    auto load_tile = [&](int it) {
        const __nv_bfloat16* Asrc = (it < nk) ? A0 : A1;
        const __nv_bfloat16* Wsrc = (it < nk) ? W0 : W1;
        int kb = (it >= nk ? it - nk : it) << 6;
#pragma unroll
        for (int i = 0; i < 4; i++) {
            int gr = bm * 128 + arow[i];
            ra[i] = make_uint4(0u, 0u, 0u, 0u);
            if (gr < M) ra[i] = *reinterpret_cast<const uint4*>(Asrc + (size_t)gr * Ka + kb + ac8[i] * 8);
        }
#pragma unroll
        for (int i = 0; i < 2; i++) {
            int gj = bn * 64 + wrow[i];
            rw[i] = *reinterpret_cast<const uint4*>(Wsrc + (size_t)gj * Ka + kb + wc8[i] * 8);
        }
    };
    auto store_tile = [&]() {
#pragma unroll
        for (int i = 0; i < 4; i++)
            *reinterpret_cast<uint4*>(&As2[arow[i]][ac8[i] * 4]) = ra[i];
#pragma unroll
        for (int i = 0; i < 2; i++)
            *reinterpret_cast<uint4*>(&Ws2[wrow[i]][wc8[i] * 4]) = rw[i];
    };

    float c[2][4][4];
#pragma unroll
    for (int i = 0; i < 2; i++)
#pragma unroll
        for (int j = 0; j < 4; j++)
#pragma unroll
            for (int k = 0; k < 4; k++) c[i][j][k] = 0.f;

    load_tile(0);
    store_tile();
    __syncthreads();

    for (int it = 0; it < nt; it++) {
        if (it + 1 < nt) load_tile(it + 1);
#pragma unroll
        for (int kk2 = 0; kk2 < 32; kk2 += 8) {
            unsigned a[2][4], bfr[4][2];
#pragma unroll
            for (int mi = 0; mi < 2; mi++) {
                int rm = wm * 32 + mi * 16;
                a[mi][0] = As2[rm + g][kk2 + tg];
                a[mi][1] = As2[rm + g + 8][kk2 + tg];
                a[mi][2] = As2[rm + g][kk2 + tg + 4];
                a[mi][3] = As2[rm + g + 8][kk2 + tg + 4];
            }
#pragma unroll
            for (int ni = 0; ni < 4; ni++) {
                int jn = wn * 32 + ni * 8 + g;
                bfr[ni][0] = Ws2[jn][kk2 + tg];
                bfr[ni][1] = Ws2[jn][kk2 + tg + 4];
            }
#pragma unroll
            for (int mi = 0; mi < 2; mi++)
#pragma unroll
                for (int ni = 0; ni < 4; ni++)
                    mma_bf16(c[mi][ni], a[mi], bfr[ni]);
        }
        __syncthreads();
        if (it + 1 < nt) {
            store_tile();
            __syncthreads();
        }
    }

#pragma unroll
    for (int mi = 0; mi < 2; mi++) {
        int row0 = bm * 128 + wm * 32 + mi * 16 + g;
        int row1 = row0 + 8;
        float gp0 = 0.f, gp1 = 0.f;
#pragma unroll
        for (int ni = 0; ni < 4; ni++) {
            int col = bn * 64 + wn * 32 + ni * 8 + 2 * tg;
            float b0 = bias[col], b1v = bias[col + 1];
            float v00 = fmaxf(c[mi][ni][0] + b0, 0.f);
            float v01 = fmaxf(c[mi][ni][1] + b1v, 0.f);
            float v10 = fmaxf(c[mi][ni][2] + b0, 0.f);
            float v11 = fmaxf(c[mi][ni][3] + b1v, 0.f);
            if (Wgate) {
                float w0 = Wgate[col], w1 = Wgate[col + 1];
                gp0 += v00 * w0 + v01 * w1;
                gp1 += v10 * w0 + v11 * w1;
            }
            if (row0 < M) {
                if (outb)
                    reinterpret_cast<unsigned*>(outb)[((size_t)row0 * HID + col) >> 1] = f2bf2(v00, v01);
                if (outf8)
                    *reinterpret_cast<unsigned short*>(outf8 + (size_t)row0 * HID + col) = f2_to_fp8x2(v00, v01);
            }
            if (row1 < M) {
                if (outb)
                    reinterpret_cast<unsigned*>(outb)[((size_t)row1 * HID + col) >> 1] = f2bf2(v10, v11);
                if (outf8)
                    *reinterpret_cast<unsigned short*>(outf8 + (size_t)row1 * HID + col) = f2_to_fp8x2(v10, v11);
            }
        }
        if (Wgate) {
            gp0 += __shfl_xor_sync(0xffffffff, gp0, 1);
            gp0 += __shfl_xor_sync(0xffffffff, gp0, 2);
            gp1 += __shfl_xor_sync(0xffffffff, gp1, 1);
            gp1 += __shfl_xor_sync(0xffffffff, gp1, 2);
            if (tg == 0) {
                if (row0 < M) atomicAdd(&gate[row0], gp0);
                if (row1 < M) atomicAdd(&gate[row1], gp1);
            }
        }
    }
}

// ---------------- pool stats ----------------
__global__ void pool_stats_kernel(const float* __restrict__ gate, const int* __restrict__ batch) {
    int b = blockIdx.x, tid = threadIdx.x;
    __shared__ int sb[2];
    if (tid < 2) sb[tid] = bsearch_batch(batch, b + tid);
    __syncthreads();
    int beg = sb[0], end = sb[1];
    __shared__ float red[256];

    float m = -3.4e38f;
    for (int n = beg + tid; n < end; n += 256) m = fmaxf(m, gate[n]);
    red[tid] = m; __syncthreads();
    for (int o = 128; o > 0; o >>= 1) { if (tid < o) red[tid] = fmaxf(red[tid], red[tid + o]); __syncthreads(); }
    float mx = red[0]; __syncthreads();

    float s = 0.f;
    for (int n = beg + tid; n < end; n += 256) s += expf(gate[n] - mx);
    red[tid] = s; __syncthreads();
    for (int o = 128; o > 0; o >>= 1) { if (tid < o) red[tid] += red[tid + o]; __syncthreads(); }

    if (tid == 0) { d_pmax[b] = mx; d_psum[b] = fmaxf(red[0], 1e-38f); }
    d_pooled[b * HID + tid] = 0.f;
}

// ---------------- pool accumulate (bf16 h) ----------------
#define PSPLIT 8
__global__ __launch_bounds__(64) void pool_acc_kernel(const __nv_bfloat16* __restrict__ h,
                                                      const float* __restrict__ gate,
                                                      const int* __restrict__ batch) {
    int b = blockIdx.x, sp = blockIdx.y, t = threadIdx.x;
    __shared__ int sb[2];
    if (t < 2) sb[t] = bsearch_batch(batch, b + t);
    __syncthreads();
    int beg = sb[0], end = sb[1];
    float mx = d_pmax[b];
    float inv = 1.0f / d_psum[b];
    const uint2* h2 = reinterpret_cast<const uint2*>(h);
    float a0 = 0.f, a1 = 0.f, a2 = 0.f, a3 = 0.f;
    for (int n = beg + sp; n < end; n += PSPLIT) {
        float w = __expf(gate[n] - mx) * inv;
        uint2 v = h2[(size_t)n * 64 + t];
        float2 f0 = bf2f(v.x), f1 = bf2f(v.y);
        a0 += w * f0.x; a1 += w * f0.y; a2 += w * f1.x; a3 += w * f1.y;
    }
    float* p = &d_pooled[b * HID + t * 4];
    atomicAdd(p + 0, a0);
    atomicAdd(p + 1, a1);
    atomicAdd(p + 2, a2);
    atomicAdd(p + 3, a3);
}

// ---------------- MLP head + log_softmax ----------------
__global__ void head_kernel(const float* __restrict__ W1, const float* __restrict__ b1,
                            const float* __restrict__ W2, const float* __restrict__ b2,
                            float* __restrict__ out) {
    int b = blockIdx.x, t = threadIdx.x;
    __shared__ float pin[HID], m1[HID];
    __shared__ float logits[NC];
    pin[t] = d_pooled[b * HID + t];
    __syncthreads();
    float acc = b1[t];
#pragma unroll 8
    for (int k = 0; k < HID; k++) acc += pin[k] * W1[t * HID + k];
    m1[t] = fmaxf(acc, 0.f);
    __syncthreads();
    if (t < NC) {
        float a = b2[t];
        for (int k = 0; k < HID; k++) a += m1[k] * W2[t * HID + k];
        logits[t] = a;
    }
    __syncthreads();
    if (t == 0) {
        float mx = logits[0];
        for (int c2 = 1; c2 < NC; c2++) mx = fmaxf(mx, logits[c2]);
        float s = 0.f;
        for (int c2 = 0; c2 < NC; c2++) s += expf(logits[c2] - mx);
        float lse = mx + logf(s);
        for (int c2 = 0; c2 < NC; c2++) out[b * NC + c2] = logits[c2] - lse;
    }
}

// ---------------- launch ----------------
extern "C" void kernel_launch(void* const* d_in, const int* in_sizes, int n_in,
                              void* d_out, int out_size) {
    const float* x      = (const float*)d_in[0];
    const int* ei       = (const int*)d_in[1];
    const int* batch    = (const int*)d_in[2];
    const float* W1l = (const float*)d_in[3];
    const float* b1l = (const float*)d_in[4];
    const float* W1r = (const float*)d_in[5];
    const float* W2l = (const float*)d_in[6];
    const float* b2l = (const float*)d_in[7];
    const float* W2r = (const float*)d_in[8];
    const float* W3l = (const float*)d_in[9];
    const float* b3l = (const float*)d_in[10];
    const float* W3r = (const float*)d_in[11];
    const float* Wg  = (const float*)d_in[12];
    const float* bg  = (const float*)d_in[13];
    const float* Wl1 = (const float*)d_in[14];
    const float* bl1 = (const float*)d_in[15];
    const float* Wl2 = (const float*)d_in[16];
    const float* bl2 = (const float*)d_in[17];
    float* out = (float*)d_out;

    void *p_aggb_, *p_hb1_, *p_hb2_, *p_xb_, *p_xf8_, *p_hf8_, *p_wb_, *p_gate_;
    cudaGetSymbolAddress(&p_aggb_, d_aggb);
    cudaGetSymbolAddress(&p_hb1_, d_hb1);
    cudaGetSymbolAddress(&p_hb2_, d_hb2);
    cudaGetSymbolAddress(&p_xb_, d_xb);
    cudaGetSymbolAddress(&p_xf8_, d_xf8);
    cudaGetSymbolAddress(&p_hf8_, d_hf8);
    cudaGetSymbolAddress(&p_wb_, d_wb);
    cudaGetSymbolAddress(&p_gate_, d_gate);
    __nv_bfloat16* p_aggb = (__nv_bfloat16*)p_aggb_;
    __nv_bfloat16* p_hb1 = (__nv_bfloat16*)p_hb1_;
    __nv_bfloat16* p_hb2 = (__nv_bfloat16*)p_hb2_;
    __nv_bfloat16* p_xb = (__nv_bfloat16*)p_xb_;
    unsigned char* p_xf8 = (unsigned char*)p_xf8_;
    unsigned char* p_hf8 = (unsigned char*)p_hf8_;
    __nv_bfloat16* p_wb = (__nv_bfloat16*)p_wb_;
    float* p_gate = (float*)p_gate_;

    const int e4blocks = (E_EDGES / 4 + 255) / 256;
    const int nwarp_blocks = (N_NODES + 7) / 8;
    const int nscan_blocks = (N_NODES + 255) / 256;

    // converts + init
    convert_x_kernel<<<(N_NODES * F_IN / 4 + 255) / 256, 256>>>(x, bg);
    convert_w_kernel<<<(W_TOTAL + 255) / 256, 256>>>(W1l, W1r, W2l, W2r, W3l, W3r);

    // CSR build
    hist_kernel<<<e4blocks, 256>>>(ei);
    scan_atomic_kernel<<<nscan_blocks, 256>>>();
    fill_kernel<<<e4blocks, 256>>>(ei);

    dim3 gemm_grid((N_NODES + 127) / 128, HID / 64);

    // layer 1
    aggregate_fp8_warp_k128<<<nwarp_blocks, 256>>>(p_xf8, p_aggb);
    sage_linear_bf16<<<gemm_grid, 256>>>(p_aggb, p_xb, p_wb + OFF_W1L, p_wb + OFF_W1R,
                                         b1l, p_hb1, p_hf8, nullptr, nullptr, N_NODES, F_IN);
    // layer 2
    aggregate_fp8_warp_k256<<<nwarp_blocks, 256>>>(p_hf8, p_aggb);
    sage_linear_bf16<<<gemm_grid, 256>>>(p_aggb, p_hb1, p_wb + OFF_W2L, p_wb + OFF_W2R,
                                         b2l, p_hb2, p_hf8, nullptr, nullptr, N_NODES, HID);
    // layer 3
    aggregate_fp8_warp_k256<<<nwarp_blocks, 256>>>(p_hf8, p_aggb);
    sage_linear_bf16<<<gemm_grid, 256>>>(p_aggb, p_hb2, p_wb + OFF_W3L, p_wb + OFF_W3R,
                                         b3l, p_hb1, nullptr, Wg, p_gate, N_NODES, HID);

    // pooling + head
    pool_stats_kernel<<<NB, 256>>>(p_gate, batch);
    pool_acc_kernel<<<dim3(NB, PSPLIT), 64>>>(p_hb1, p_gate, batch);
    head_kernel<<<NB, HID>>>(Wl1, bl1, Wl2, bl2, out);
}

// round 17
// speedup vs baseline: 1.0597x; 1.0110x over previous
#include <cuda_runtime.h>
#include <cuda_bf16.h>
#include <cuda_fp16.h>
#include <cuda_fp8.h>
#include <math.h>

#define N_NODES 50000
#define E_EDGES 1600000
#define HID 256
#define F_IN 128
#define NB 64
#define NC 10

// ---------------- static device scratch ----------------
__device__ __nv_bfloat16 d_aggb[(size_t)N_NODES * HID];
__device__ __nv_bfloat16 d_hb1[(size_t)N_NODES * HID];
__device__ __nv_bfloat16 d_hb2[(size_t)N_NODES * HID];
__device__ __nv_bfloat16 d_xb[(size_t)N_NODES * F_IN];
__device__ __align__(16) unsigned char d_xf8[(size_t)N_NODES * F_IN];
__device__ __align__(16) unsigned char d_hf8[(size_t)N_NODES * HID];
__device__ __nv_bfloat16 d_wb[327680];
__device__ int   d_deg[N_NODES];
__device__ float d_invdeg[N_NODES];
__device__ int   d_rowptr[N_NODES];
__device__ int   d_cursor[N_NODES];
__device__ int   d_srcs[E_EDGES];
__device__ int   d_counter;
__device__ float d_gate[N_NODES];
__device__ float d_pooled[NB * HID];
__device__ float d_pmax[NB];
__device__ float d_psum[NB];

#define OFF_W1L 0
#define OFF_W1R 32768
#define OFF_W2L 65536
#define OFF_W2R 131072
#define OFF_W3L 196608
#define OFF_W3R 262144
#define W_TOTAL 327680

// dynamic smem layout for GEMM: [As0 | Ws0 | As1 | Ws1]
#define AS_WORDS (128 * 36)
#define WS_WORDS (64 * 36)
#define BUF_WORDS (AS_WORDS + WS_WORDS)
#define GEMM_SMEM_BYTES (2 * BUF_WORDS * 4)

__device__ __forceinline__ unsigned f2bf2(float a, float b) {
    __nv_bfloat162 p = __floats2bfloat162_rn(a, b);
    return *reinterpret_cast<unsigned*>(&p);
}
__device__ __forceinline__ float2 bf2f(unsigned u) {
    __nv_bfloat162 b = *reinterpret_cast<__nv_bfloat162*>(&u);
    return __bfloat1622float2(b);
}
__device__ __forceinline__ __half2 fp8x2_to_h2(unsigned short u) {
    __half2_raw hr = __nv_cvt_fp8x2_to_halfraw2((__nv_fp8x2_storage_t)u, __NV_E4M3);
    return *reinterpret_cast<__half2*>(&hr);
}
__device__ __forceinline__ unsigned short f2_to_fp8x2(float a, float b) {
    float2 f = make_float2(a, b);
    return (unsigned short)__nv_cvt_float2_to_fp8x2(f, __NV_SATFINITE, __NV_E4M3);
}
__device__ __forceinline__ void acc16h(__half2* acc, uint4 v) {
    unsigned w[4] = {v.x, v.y, v.z, v.w};
#pragma unroll
    for (int q = 0; q < 4; q++) {
        acc[2 * q]     = __hadd2(acc[2 * q],     fp8x2_to_h2((unsigned short)w[q]));
        acc[2 * q + 1] = __hadd2(acc[2 * q + 1], fp8x2_to_h2((unsigned short)(w[q] >> 16)));
    }
}
__device__ __forceinline__ __half2 h2shfl_xor(__half2 v, int m) {
    unsigned u = *reinterpret_cast<unsigned*>(&v);
    u = __shfl_xor_sync(0xffffffff, u, m);
    return *reinterpret_cast<__half2*>(&u);
}
__device__ __forceinline__ int bsearch_batch(const int* batch, int key) {
    int lo = 0, hi = N_NODES;
    while (lo < hi) {
        int mid = (lo + hi) >> 1;
        if (batch[mid] < key) lo = mid + 1; else hi = mid;
    }
    return lo;
}

// ---------------- CSR build (4 edges/thread) ----------------
__global__ void hist_kernel(const int* __restrict__ ei) {
    int e4 = (blockIdx.x * blockDim.x + threadIdx.x) * 4;
    if (e4 >= E_EDGES) return;
    int4 d = *reinterpret_cast<const int4*>(ei + E_EDGES + e4);
    if ((unsigned)d.x < (unsigned)N_NODES) atomicAdd(&d_deg[d.x], 1);
    if ((unsigned)d.y < (unsigned)N_NODES) atomicAdd(&d_deg[d.y], 1);
    if ((unsigned)d.z < (unsigned)N_NODES) atomicAdd(&d_deg[d.z], 1);
    if ((unsigned)d.w < (unsigned)N_NODES) atomicAdd(&d_deg[d.w], 1);
}

__global__ void scan_atomic_kernel() {
    __shared__ int sd[256];
    __shared__ int base;
    int tid = threadIdx.x;
    int i = blockIdx.x * 256 + tid;
    int v = (i < N_NODES) ? d_deg[i] : 0;
    sd[tid] = v;
    __syncthreads();
    for (int off = 1; off < 256; off <<= 1) {
        int t = (tid >= off) ? sd[tid - off] : 0;
        __syncthreads();
        sd[tid] += t;
        __syncthreads();
    }
    if (tid == 255) base = atomicAdd(&d_counter, sd[255]);
    __syncthreads();
    if (i < N_NODES) {
        int excl = base + sd[tid] - v;
        d_rowptr[i] = excl;
        d_cursor[i] = excl;
        d_invdeg[i] = 1.0f / (float)max(v, 1);
    }
}

__global__ void fill_kernel(const int* __restrict__ ei) {
    int e4 = (blockIdx.x * blockDim.x + threadIdx.x) * 4;
    if (e4 >= E_EDGES) return;
    int4 s = *reinterpret_cast<const int4*>(ei + e4);
    int4 d = *reinterpret_cast<const int4*>(ei + E_EDGES + e4);
    if ((unsigned)d.x < (unsigned)N_NODES && (unsigned)s.x < (unsigned)N_NODES)
        d_srcs[atomicAdd(&d_cursor[d.x], 1)] = s.x;
    if ((unsigned)d.y < (unsigned)N_NODES && (unsigned)s.y < (unsigned)N_NODES)
        d_srcs[atomicAdd(&d_cursor[d.y], 1)] = s.y;
    if ((unsigned)d.z < (unsigned)N_NODES && (unsigned)s.z < (unsigned)N_NODES)
        d_srcs[atomicAdd(&d_cursor[d.z], 1)] = s.z;
    if ((unsigned)d.w < (unsigned)N_NODES && (unsigned)s.w < (unsigned)N_NODES)
        d_srcs[atomicAdd(&d_cursor[d.w], 1)] = s.w;
}

// ---------------- merged converts (+ deg/gate/counter init) ----------------
__global__ void convert_all_kernel(const float* __restrict__ x, const float* __restrict__ bg,
                                   const float* __restrict__ W1l, const float* __restrict__ W1r,
                                   const float* __restrict__ W2l, const float* __restrict__ W2r,
                                   const float* __restrict__ W3l, const float* __restrict__ W3r) {
    int i = blockIdx.x * blockDim.x + threadIdx.x;
    if (i == 0) d_counter = 0;
    if (i < N_NODES) { d_deg[i] = 0; d_gate[i] = bg[0]; }
    if (i < W_TOTAL) {
        float v;
        if      (i < OFF_W1R) v = W1l[i - OFF_W1L];
        else if (i < OFF_W2L) v = W1r[i - OFF_W1R];
        else if (i < OFF_W2R) v = W2l[i - OFF_W2L];
        else if (i < OFF_W3L) v = W2r[i - OFF_W2R];
        else if (i < OFF_W3R) v = W3l[i - OFF_W3L];
        else                  v = W3r[i - OFF_W3R];
        d_wb[i] = __float2bfloat16_rn(v);
    }
    if (i >= N_NODES * F_IN / 4) return;
    float4 v = reinterpret_cast<const float4*>(x)[i];
    uint2 o;
    o.x = f2bf2(v.x, v.y);
    o.y = f2bf2(v.z, v.w);
    reinterpret_cast<uint2*>(d_xb)[i] = o;
    unsigned p8 = (unsigned)f2_to_fp8x2(v.x, v.y) | ((unsigned)f2_to_fp8x2(v.z, v.w) << 16);
    reinterpret_cast<unsigned*>(d_xf8)[i] = p8;
}

// ---------------- warp-per-node fp8 gather (half2 accumulate), K=256 ----------------
__global__ __launch_bounds__(256) void aggregate_fp8_warp_k256(const unsigned char* __restrict__ xin,
                                                               __nv_bfloat16* __restrict__ agg) {
    int wid = threadIdx.x >> 5;
    int n = blockIdx.x * 8 + wid;
    if (n >= N_NODES) return;
    int lane = threadIdx.x & 31;
    int slot = lane & 15, grp = lane >> 4;
    int beg = d_rowptr[n], end = beg + d_deg[n];
    const uint4* __restrict__ x4 = reinterpret_cast<const uint4*>(xin);

    __half2 acc[8];
#pragma unroll
    for (int k = 0; k < 8; k++) acc[k] = __half2half2(__ushort_as_half(0));

    for (int base = beg; base < end; base += 32) {
        int cnt = min(32, end - base);
        int my = (lane < cnt) ? d_srcs[base + lane] : 0;
        for (int jb = 0; jb < cnt; jb += 8) {
            int j0 = jb + grp, j1 = jb + 2 + grp, j2 = jb + 4 + grp, j3 = jb + 6 + grp;
            int s0 = __shfl_sync(0xffffffff, my, j0);
            int s1 = __shfl_sync(0xffffffff, my, j1);
            int s2 = __shfl_sync(0xffffffff, my, j2);
            int s3 = __shfl_sync(0xffffffff, my, j3);
            if (j3 < cnt) {
                acc16h(acc, x4[(size_t)s0 * 16 + slot]);
                acc16h(acc, x4[(size_t)s1 * 16 + slot]);
                acc16h(acc, x4[(size_t)s2 * 16 + slot]);
                acc16h(acc, x4[(size_t)s3 * 16 + slot]);
            } else {
                if (j0 < cnt) acc16h(acc, x4[(size_t)s0 * 16 + slot]);
                if (j1 < cnt) acc16h(acc, x4[(size_t)s1 * 16 + slot]);
                if (j2 < cnt) acc16h(acc, x4[(size_t)s2 * 16 + slot]);
            }
        }
    }

#pragma unroll
    for (int k = 0; k < 8; k++) acc[k] = __hadd2(acc[k], h2shfl_xor(acc[k], 16));

    if (grp == 0) {
        float inv = d_invdeg[n];
        float f[16];
#pragma unroll
        for (int k = 0; k < 8; k++) {
            float2 t = __half22float2(acc[k]);
            f[2 * k] = t.x * inv;
            f[2 * k + 1] = t.y * inv;
        }
        uint4 o0, o1;
        o0.x = f2bf2(f[0], f[1]);   o0.y = f2bf2(f[2], f[3]);
        o0.z = f2bf2(f[4], f[5]);   o0.w = f2bf2(f[6], f[7]);
        o1.x = f2bf2(f[8], f[9]);   o1.y = f2bf2(f[10], f[11]);
        o1.z = f2bf2(f[12], f[13]); o1.w = f2bf2(f[14], f[15]);
        uint4* ag4 = reinterpret_cast<uint4*>(agg);
        ag4[(size_t)n * 32 + slot * 2]     = o0;
        ag4[(size_t)n * 32 + slot * 2 + 1] = o1;
    }
}

// ---------------- warp-per-node fp8 gather (half2 accumulate), K=128 ----------------
__global__ __launch_bounds__(256) void aggregate_fp8_warp_k128(const unsigned char* __restrict__ xin,
                                                               __nv_bfloat16* __restrict__ agg) {
    int wid = threadIdx.x >> 5;
    int n = blockIdx.x * 8 + wid;
    if (n >= N_NODES) return;
    int lane = threadIdx.x & 31;
    int slot = lane & 7, grp = lane >> 3;
    int beg = d_rowptr[n], end = beg + d_deg[n];
    const uint4* __restrict__ x4 = reinterpret_cast<const uint4*>(xin);

    __half2 acc[8];
#pragma unroll
    for (int k = 0; k < 8; k++) acc[k] = __half2half2(__ushort_as_half(0));

    for (int base = beg; base < end; base += 32) {
        int cnt = min(32, end - base);
        int my = (lane < cnt) ? d_srcs[base + lane] : 0;
        for (int jb = 0; jb < cnt; jb += 8) {
            int j0 = jb + grp, j1 = jb + 4 + grp;
            int s0 = __shfl_sync(0xffffffff, my, j0);
            int s1 = __shfl_sync(0xffffffff, my, j1);
            if (j1 < cnt) {
                acc16h(acc, x4[(size_t)s0 * 8 + slot]);
                acc16h(acc, x4[(size_t)s1 * 8 + slot]);
            } else if (j0 < cnt) {
                acc16h(acc, x4[(size_t)s0 * 8 + slot]);
            }
        }
    }

#pragma unroll
    for (int k = 0; k < 8; k++) {
        acc[k] = __hadd2(acc[k], h2shfl_xor(acc[k], 8));
        acc[k] = __hadd2(acc[k], h2shfl_xor(acc[k], 16));
    }

    if (grp == 0) {
        float inv = d_invdeg[n];
        float f[16];
#pragma unroll
        for (int k = 0; k < 8; k++) {
            float2 t = __half22float2(acc[k]);
            f[2 * k] = t.x * inv;
            f[2 * k + 1] = t.y * inv;
        }
        uint4 o0, o1;
        o0.x = f2bf2(f[0], f[1]);   o0.y = f2bf2(f[2], f[3]);
        o0.z = f2bf2(f[4], f[5]);   o0.w = f2bf2(f[6], f[7]);
        o1.x = f2bf2(f[8], f[9]);   o1.y = f2bf2(f[10], f[11]);
        o1.z = f2bf2(f[12], f[13]); o1.w = f2bf2(f[14], f[15]);
        uint4* ag4 = reinterpret_cast<uint4*>(agg);
        ag4[(size_t)n * 16 + slot * 2]     = o0;
        ag4[(size_t)n * 16 + slot * 2 + 1] = o1;
    }
}

// ---------------- bf16 tensor-core fused SAGE linear (double-buffered smem) ----------------
__device__ __forceinline__ void mma_bf16(float c[4], const unsigned a[4], const unsigned b[2]) {
    asm volatile(
        "mma.sync.aligned.m16n8k16.row.col.f32.bf16.bf16.f32 "
        "{%0,%1,%2,%3}, {%4,%5,%6,%7}, {%8,%9}, {%0,%1,%2,%3};"
        : "+f"(c[0]), "+f"(c[1]), "+f"(c[2]), "+f"(c[3])
        : "r"(a[0]), "r"(a[1]), "r"(a[2]), "r"(a[3]), "r"(b[0]), "r"(b[1]));
}

__global__ __launch_bounds__(256) void sage_linear_bf16(
    const __nv_bfloat16* __restrict__ A0, const __nv_bfloat16* __restrict__ A1,
    const __nv_bfloat16* __restrict__ W0, const __nv_bfloat16* __restrict__ W1,
    const float* __restrict__ bias,
    __nv_bfloat16* __restrict__ outb, unsigned char* __restrict__ outf8,
    const float* __restrict__ Wgate, float* __restrict__ gate,
    int M, int Ka)
{
    extern __shared__ unsigned smemu[];
    int tid = threadIdx.x;
    int wid = tid >> 5, lane = tid & 31;
    int wm = wid & 3, wn = wid >> 2;
    int g = lane >> 2, tg = lane & 3;
    int bm = blockIdx.x, bn = blockIdx.y;

    const int nk = Ka >> 6;
    const int nt = 2 * nk;

    int arow[4], ac8[4], wrow[2], wc8[2];
#pragma unroll
    for (int i = 0; i < 4; i++) {
        int l = tid + i * 256;
        arow[i] = l >> 3; ac8[i] = l & 7;
    }
#pragma unroll
    for (int i = 0; i < 2; i++) {
        int l = tid + i * 256;
        wrow[i] = l >> 3; wc8[i] = l & 7;
    }

    uint4 ra[4], rw[2];
    auto load_tile = [&](int it) {
        const __nv_bfloat16* Asrc = (it < nk) ? A0 : A1;
        const __nv_bfloat16* Wsrc = (it < nk) ? W0 : W1;
        int kb = (it >= nk ? it - nk : it) << 6;
#pragma unroll
        for (int i = 0; i < 4; i++) {
            int gr = bm * 128 + arow[i];
            ra[i] = make_uint4(0u, 0u, 0u, 0u);
            if (gr < M) ra[i] = *reinterpret_cast<const uint4*>(Asrc + (size_t)gr * Ka + kb + ac8[i] * 8);
        }
#pragma unroll
        for (int i = 0; i < 2; i++) {
            int gj = bn * 64 + wrow[i];
            rw[i] = *reinterpret_cast<const uint4*>(Wsrc + (size_t)gj * Ka + kb + wc8[i] * 8);
        }
    };
    auto store_tile = [&](int buf) {
        unsigned* As = smemu + buf * BUF_WORDS;
        unsigned* Ws = As + AS_WORDS;
#pragma unroll
        for (int i = 0; i < 4; i++)
            *reinterpret_cast<uint4*>(&As[arow[i] * 36 + ac8[i] * 4]) = ra[i];
#pragma unroll
        for (int i = 0; i < 2; i++)
            *reinterpret_cast<uint4*>(&Ws[wrow[i] * 36 + wc8[i] * 4]) = rw[i];
    };

    float c[2][4][4];
#pragma unroll
    for (int i = 0; i < 2; i++)
#pragma unroll
        for (int j = 0; j < 4; j++)
#pragma unroll
            for (int k = 0; k < 4; k++) c[i][j][k] = 0.f;

    load_tile(0);
    store_tile(0);
    if (nt > 1) load_tile(1);
    __syncthreads();

    for (int it = 0; it < nt; it++) {
        int cur = it & 1;
        if (it + 1 < nt) store_tile((it + 1) & 1);   // regs hold tile(it+1); writes unused buffer
        if (it + 2 < nt) load_tile(it + 2);          // prefetch global -> regs
        const unsigned* As = smemu + cur * BUF_WORDS;
        const unsigned* Ws = As + AS_WORDS;
#pragma unroll
        for (int kk2 = 0; kk2 < 32; kk2 += 8) {
            unsigned a[2][4], bfr[4][2];
#pragma unroll
            for (int mi = 0; mi < 2; mi++) {
                int rm = wm * 32 + mi * 16;
                a[mi][0] = As[(rm + g) * 36 + kk2 + tg];
                a[mi][1] = As[(rm + g + 8) * 36 + kk2 + tg];
                a[mi][2] = As[(rm + g) * 36 + kk2 + tg + 4];
                a[mi][3] = As[(rm + g + 8) * 36 + kk2 + tg + 4];
            }
#pragma unroll
            for (int ni = 0; ni < 4; ni++) {
                int jn = wn * 32 + ni * 8 + g;
                bfr[ni][0] = Ws[jn * 36 + kk2 + tg];
                bfr[ni][1] = Ws[jn * 36 + kk2 + tg + 4];
            }
#pragma unroll
            for (int mi = 0; mi < 2; mi++)
#pragma unroll
                for (int ni = 0; ni < 4; ni++)
                    mma_bf16(c[mi][ni], a[mi], bfr[ni]);
        }
        __syncthreads();
    }

#pragma unroll
    for (int mi = 0; mi < 2; mi++) {
        int row0 = bm * 128 + wm * 32 + mi * 16 + g;
        int row1 = row0 + 8;
        float gp0 = 0.f, gp1 = 0.f;
#pragma unroll
        for (int ni = 0; ni < 4; ni++) {
            int col = bn * 64 + wn * 32 + ni * 8 + 2 * tg;
            float b0 = bias[col], b1v = bias[col + 1];
            float v00 = fmaxf(c[mi][ni][0] + b0, 0.f);
            float v01 = fmaxf(c[mi][ni][1] + b1v, 0.f);
            float v10 = fmaxf(c[mi][ni][2] + b0, 0.f);
            float v11 = fmaxf(c[mi][ni][3] + b1v, 0.f);
            if (Wgate) {
                float w0 = Wgate[col], w1 = Wgate[col + 1];
                gp0 += v00 * w0 + v01 * w1;
                gp1 += v10 * w0 + v11 * w1;
            }
            if (row0 < M) {
                if (outb)
                    reinterpret_cast<unsigned*>(outb)[((size_t)row0 * HID + col) >> 1] = f2bf2(v00, v01);
                if (outf8)
                    *reinterpret_cast<unsigned short*>(outf8 + (size_t)row0 * HID + col) = f2_to_fp8x2(v00, v01);
            }
            if (row1 < M) {
                if (outb)
                    reinterpret_cast<unsigned*>(outb)[((size_t)row1 * HID + col) >> 1] = f2bf2(v10, v11);
                if (outf8)
                    *reinterpret_cast<unsigned short*>(outf8 + (size_t)row1 * HID + col) = f2_to_fp8x2(v10, v11);
            }
        }
        if (Wgate) {
            gp0 += __shfl_xor_sync(0xffffffff, gp0, 1);
            gp0 += __shfl_xor_sync(0xffffffff, gp0, 2);
            gp1 += __shfl_xor_sync(0xffffffff, gp1, 1);
            gp1 += __shfl_xor_sync(0xffffffff, gp1, 2);
            if (tg == 0) {
                if (row0 < M) atomicAdd(&gate[row0], gp0);
                if (row1 < M) atomicAdd(&gate[row1], gp1);
            }
        }
    }
}

// ---------------- pool stats ----------------
__global__ void pool_stats_kernel(const float* __restrict__ gate, const int* __restrict__ batch) {
    int b = blockIdx.x, tid = threadIdx.x;
    __shared__ int sb[2];
    if (tid < 2) sb[tid] = bsearch_batch(batch, b + tid);
    __syncthreads();
    int beg = sb[0], end = sb[1];
    __shared__ float red[256];

    float m = -3.4e38f;
    for (int n = beg + tid; n < end; n += 256) m = fmaxf(m, gate[n]);
    red[tid] = m; __syncthreads();
    for (int o = 128; o > 0; o >>= 1) { if (tid < o) red[tid] = fmaxf(red[tid], red[tid + o]); __syncthreads(); }
    float mx = red[0]; __syncthreads();

    float s = 0.f;
    for (int n = beg + tid; n < end; n += 256) s += expf(gate[n] - mx);
    red[tid] = s; __syncthreads();
    for (int o = 128; o > 0; o >>= 1) { if (tid < o) red[tid] += red[tid + o]; __syncthreads(); }

    if (tid == 0) { d_pmax[b] = mx; d_psum[b] = fmaxf(red[0], 1e-38f); }
    d_pooled[b * HID + tid] = 0.f;
}

// ---------------- pool accumulate (bf16 h) ----------------
#define PSPLIT 8
__global__ __launch_bounds__(64) void pool_acc_kernel(const __nv_bfloat16* __restrict__ h,
                                                      const float* __restrict__ gate,
                                                      const int* __restrict__ batch) {
    int b = blockIdx.x, sp = blockIdx.y, t = threadIdx.x;
    __shared__ int sb[2];
    if (t < 2) sb[t] = bsearch_batch(batch, b + t);
    __syncthreads();
    int beg = sb[0], end = sb[1];
    float mx = d_pmax[b];
    float inv = 1.0f / d_psum[b];
    const uint2* h2 = reinterpret_cast<const uint2*>(h);
    float a0 = 0.f, a1 = 0.f, a2 = 0.f, a3 = 0.f;
    for (int n = beg + sp; n < end; n += PSPLIT) {
        float w = __expf(gate[n] - mx) * inv;
        uint2 v = h2[(size_t)n * 64 + t];
        float2 f0 = bf2f(v.x), f1 = bf2f(v.y);
        a0 += w * f0.x; a1 += w * f0.y; a2 += w * f1.x; a3 += w * f1.y;
    }
    float* p = &d_pooled[b * HID + t * 4];
    atomicAdd(p + 0, a0);
    atomicAdd(p + 1, a1);
    atomicAdd(p + 2, a2);
    atomicAdd(p + 3, a3);
}

// ---------------- MLP head + log_softmax ----------------
__global__ void head_kernel(const float* __restrict__ W1, const float* __restrict__ b1,
                            const float* __restrict__ W2, const float* __restrict__ b2,
                            float* __restrict__ out) {
    int b = blockIdx.x, t = threadIdx.x;
    __shared__ float pin[HID], m1[HID];
    __shared__ float logits[NC];
    pin[t] = d_pooled[b * HID + t];
    __syncthreads();
    float acc = b1[t];
#pragma unroll 8
    for (int k = 0; k < HID; k++) acc += pin[k] * W1[t * HID + k];
    m1[t] = fmaxf(acc, 0.f);
    __syncthreads();
    if (t < NC) {
        float a = b2[t];
        for (int k = 0; k < HID; k++) a += m1[k] * W2[t * HID + k];
        logits[t] = a;
    }
    __syncthreads();
    if (t == 0) {
        float mx = logits[0];
        for (int c2 = 1; c2 < NC; c2++) mx = fmaxf(mx, logits[c2]);
        float s = 0.f;
        for (int c2 = 0; c2 < NC; c2++) s += expf(logits[c2] - mx);
        float lse = mx + logf(s);
        for (int c2 = 0; c2 < NC; c2++) out[b * NC + c2] = logits[c2] - lse;
    }
}

// ---------------- launch ----------------
extern "C" void kernel_launch(void* const* d_in, const int* in_sizes, int n_in,
                              void* d_out, int out_size) {
    const float* x      = (const float*)d_in[0];
    const int* ei       = (const int*)d_in[1];
    const int* batch    = (const int*)d_in[2];
    const float* W1l = (const float*)d_in[3];
    const float* b1l = (const float*)d_in[4];
    const float* W1r = (const float*)d_in[5];
    const float* W2l = (const float*)d_in[6];
    const float* b2l = (const float*)d_in[7];
    const float* W2r = (const float*)d_in[8];
    const float* W3l = (const float*)d_in[9];
    const float* b3l = (const float*)d_in[10];
    const float* W3r = (const float*)d_in[11];
    const float* Wg  = (const float*)d_in[12];
    const float* bg  = (const float*)d_in[13];
    const float* Wl1 = (const float*)d_in[14];
    const float* bl1 = (const float*)d_in[15];
    const float* Wl2 = (const float*)d_in[16];
    const float* bl2 = (const float*)d_in[17];
    float* out = (float*)d_out;

    void *p_aggb_, *p_hb1_, *p_hb2_, *p_xb_, *p_xf8_, *p_hf8_, *p_wb_, *p_gate_;
    cudaGetSymbolAddress(&p_aggb_, d_aggb);
    cudaGetSymbolAddress(&p_hb1_, d_hb1);
    cudaGetSymbolAddress(&p_hb2_, d_hb2);
    cudaGetSymbolAddress(&p_xb_, d_xb);
    cudaGetSymbolAddress(&p_xf8_, d_xf8);
    cudaGetSymbolAddress(&p_hf8_, d_hf8);
    cudaGetSymbolAddress(&p_wb_, d_wb);
    cudaGetSymbolAddress(&p_gate_, d_gate);
    __nv_bfloat16* p_aggb = (__nv_bfloat16*)p_aggb_;
    __nv_bfloat16* p_hb1 = (__nv_bfloat16*)p_hb1_;
    __nv_bfloat16* p_hb2 = (__nv_bfloat16*)p_hb2_;
    __nv_bfloat16* p_xb = (__nv_bfloat16*)p_xb_;
    unsigned char* p_xf8 = (unsigned char*)p_xf8_;
    unsigned char* p_hf8 = (unsigned char*)p_hf8_;
    __nv_bfloat16* p_wb = (__nv_bfloat16*)p_wb_;
    float* p_gate = (float*)p_gate_;

    static bool attr_set = false;
    if (!attr_set) {
        cudaFuncSetAttribute(sage_linear_bf16, cudaFuncAttributeMaxDynamicSharedMemorySize,
                             GEMM_SMEM_BYTES);
        attr_set = true;
    }

    const int e4blocks = (E_EDGES / 4 + 255) / 256;
    const int nwarp_blocks = (N_NODES + 7) / 8;
    const int nscan_blocks = (N_NODES + 255) / 256;

    // merged converts + init
    convert_all_kernel<<<(N_NODES * F_IN / 4 + 255) / 256, 256>>>(x, bg, W1l, W1r, W2l, W2r, W3l, W3r);

    // CSR build
    hist_kernel<<<e4blocks, 256>>>(ei);
    scan_atomic_kernel<<<nscan_blocks, 256>>>();
    fill_kernel<<<e4blocks, 256>>>(ei);

    dim3 gemm_grid((N_NODES + 127) / 128, HID / 64);

    // layer 1
    aggregate_fp8_warp_k128<<<nwarp_blocks, 256>>>(p_xf8, p_aggb);
    sage_linear_bf16<<<gemm_grid, 256, GEMM_SMEM_BYTES>>>(p_aggb, p_xb, p_wb + OFF_W1L, p_wb + OFF_W1R,
                                                          b1l, p_hb1, p_hf8, nullptr, nullptr, N_NODES, F_IN);
    // layer 2
    aggregate_fp8_warp_k256<<<nwarp_blocks, 256>>>(p_hf8, p_aggb);
    sage_linear_bf16<<<gemm_grid, 256, GEMM_SMEM_BYTES>>>(p_aggb, p_hb1, p_wb + OFF_W2L, p_wb + OFF_W2R,
                                                          b2l, p_hb2, p_hf8, nullptr, nullptr, N_NODES, HID);
    // layer 3
    aggregate_fp8_warp_k256<<<nwarp_blocks, 256>>>(p_hf8, p_aggb);
    sage_linear_bf16<<<gemm_grid, 256, GEMM_SMEM_BYTES>>>(p_aggb, p_hb2, p_wb + OFF_W3L, p_wb + OFF_W3R,
                                                          b3l, p_hb1, nullptr, Wg, p_gate, N_NODES, HID);

    // pooling + head
    pool_stats_kernel<<<NB, 256>>>(p_gate, batch);
    pool_acc_kernel<<<dim3(NB, PSPLIT), 64>>>(p_hb1, p_gate, batch);
    head_kernel<<<NB, HID>>>(Wl1, bl1, Wl2, bl2, out);
}